// round 2
// baseline (speedup 1.0000x reference)
#include <cuda_runtime.h>
#include <math.h>

#define NN 50000
#define CC 128
#define HH 256
#define EE 600000

// ---- persistent scratch ----
__device__ float  g_xbuf[NN*CC];   // running residual x
__device__ float  g_hbuf[NN*CC];   // graphnorm+relu output (gen_conv input)
__device__ float  g_obuf[NN*CC];   // agg + root (MLP input)
__device__ float  g_h1  [NN*HH];   // raw hidden after W1 (LN fused into gemm2 loader)
__device__ float  g_gnstat[2*CC];
__device__ double g_lnstat[2];
__device__ int    g_deg [NN];      // degree, then reused as scatter cursor
__device__ int    g_off [NN+1];
__device__ int    g_esrc[EE];      // src node ids grouped by dst (CSR)

// =================== CSR build (dst-grouped), once per launch ===================
__global__ void k_zero_deg(int N){
    for (int i = blockIdx.x*blockDim.x + threadIdx.x; i < N; i += gridDim.x*blockDim.x)
        g_deg[i] = 0;
}
__global__ void k_hist(const int* __restrict__ dst, int E){
    for (int e = blockIdx.x*blockDim.x + threadIdx.x; e < E; e += gridDim.x*blockDim.x)
        atomicAdd(&g_deg[dst[e]], 1);
}
// single-block exclusive scan over N degrees
__global__ void k_scan(int N){
    __shared__ int part[1024];
    int t = threadIdx.x;
    int chunk = (N + 1023)/1024;
    int beg = t*chunk, end = min(beg + chunk, N);
    int s = 0;
    for (int i = beg; i < end; i++) s += g_deg[i];
    part[t] = s; __syncthreads();
    for (int o = 1; o < 1024; o <<= 1){
        int v = (t >= o) ? part[t-o] : 0;
        __syncthreads();
        part[t] += v;
        __syncthreads();
    }
    int base = (t == 0) ? 0 : part[t-1];
    for (int i = beg; i < end; i++){ g_off[i] = base; base += g_deg[i]; }
    if (t == 1023) g_off[N] = part[1023];
}
__global__ void k_scatter(const int* __restrict__ src, const int* __restrict__ dst, int E){
    for (int e = blockIdx.x*blockDim.x + threadIdx.x; e < E; e += gridDim.x*blockDim.x){
        int d = dst[e];
        int pos = atomicAdd(&g_deg[d], 1);
        g_esrc[g_off[d] + pos] = src[e];
    }
}

// =================== elementwise / norm kernels ===================
__global__ void k_copy(const float* __restrict__ x, int n){
    for (int i = blockIdx.x*blockDim.x + threadIdx.x; i < n; i += gridDim.x*blockDim.x)
        g_xbuf[i] = x[i];
}
__global__ void k_zero_stats(){
    int t = threadIdx.x;
    if (t < 2*CC) g_gnstat[t] = 0.f;
    if (t == 0){ g_lnstat[0] = 0.0; g_lnstat[1] = 0.0; }
}
__global__ void k_gn_stats(int N){
    int c = threadIdx.x;          // 128 threads = channels
    float s1 = 0.f, s2 = 0.f;
    for (int r = blockIdx.x; r < N; r += gridDim.x){
        float v = g_xbuf[(size_t)r*CC + c];
        s1 += v; s2 += v*v;
    }
    atomicAdd(&g_gnstat[c],    s1);
    atomicAdd(&g_gnstat[CC+c], s2);
}
__global__ void k_gn_apply(const float* __restrict__ gw, const float* __restrict__ gb,
                           const float* __restrict__ ga, int l, int N){
    int total = N*CC;
    float invN = 1.f/(float)N;
    for (int i = blockIdx.x*blockDim.x + threadIdx.x; i < total; i += gridDim.x*blockDim.x){
        int c = i & (CC-1);
        float mean = g_gnstat[c]*invN;
        float a = ga[l*CC+c];
        // var = E[(x - a*mean)^2] = E[x^2] - 2a*mean^2 + a^2*mean^2
        float var = g_gnstat[CC+c]*invN - 2.f*a*mean*mean + a*a*mean*mean;
        float o = g_xbuf[i] - a*mean;
        float y = gw[l*CC+c]*o*rsqrtf(var + 1e-5f) + gb[l*CC+c];
        g_hbuf[i] = fmaxf(y, 0.f);
    }
}

// =================== fused softmax-aggregate (no atomics, no max pass) ===================
// warp per dst node; lane handles 4 channels (float4). hbuf >= 0 so relu is identity.
// Unshifted softmax: z = t*(h+eps) is tiny (graph-normed), exp cannot overflow.
__global__ void k_agg(const float* __restrict__ t, int l, int N){
    int d = blockIdx.x*8 + (threadIdx.x >> 5);
    if (d >= N) return;
    int lane = threadIdx.x & 31;
    int beg = g_off[d], end = g_off[d+1];
    float tv = t[l];
    float4 num = make_float4(0.f,0.f,0.f,0.f);
    float4 den = make_float4(0.f,0.f,0.f,0.f);
    int j = beg;
    // unroll-2 with prefetched src ids for MLP
    for (; j + 1 < end; j += 2){
        int s0 = g_esrc[j], s1 = g_esrc[j+1];
        float4 v0 = *((const float4*)&g_hbuf[(size_t)s0*CC] + lane);
        float4 v1 = *((const float4*)&g_hbuf[(size_t)s1*CC] + lane);
        float m0x=v0.x+1e-7f, m0y=v0.y+1e-7f, m0z=v0.z+1e-7f, m0w=v0.w+1e-7f;
        float m1x=v1.x+1e-7f, m1y=v1.y+1e-7f, m1z=v1.z+1e-7f, m1w=v1.w+1e-7f;
        float e0x=__expf(tv*m0x), e0y=__expf(tv*m0y), e0z=__expf(tv*m0z), e0w=__expf(tv*m0w);
        float e1x=__expf(tv*m1x), e1y=__expf(tv*m1y), e1z=__expf(tv*m1z), e1w=__expf(tv*m1w);
        num.x = fmaf(m0x,e0x,fmaf(m1x,e1x,num.x)); den.x += e0x+e1x;
        num.y = fmaf(m0y,e0y,fmaf(m1y,e1y,num.y)); den.y += e0y+e1y;
        num.z = fmaf(m0z,e0z,fmaf(m1z,e1z,num.z)); den.z += e0z+e1z;
        num.w = fmaf(m0w,e0w,fmaf(m1w,e1w,num.w)); den.w += e0w+e1w;
    }
    if (j < end){
        int s0 = g_esrc[j];
        float4 v0 = *((const float4*)&g_hbuf[(size_t)s0*CC] + lane);
        float mx=v0.x+1e-7f, my=v0.y+1e-7f, mz=v0.z+1e-7f, mw=v0.w+1e-7f;
        float ex=__expf(tv*mx), ey=__expf(tv*my), ez=__expf(tv*mz), ew=__expf(tv*mw);
        num.x = fmaf(mx,ex,num.x); den.x += ex;
        num.y = fmaf(my,ey,num.y); den.y += ey;
        num.z = fmaf(mz,ez,num.z); den.z += ez;
        num.w = fmaf(mw,ew,num.w); den.w += ew;
    }
    float4 h = *((const float4*)&g_hbuf[(size_t)d*CC] + lane);
    float4 o;
    o.x = num.x/(den.x+1e-16f) + h.x;
    o.y = num.y/(den.y+1e-16f) + h.y;
    o.z = num.z/(den.z+1e-16f) + h.z;
    o.w = num.w/(den.w+1e-16f) + h.w;
    *((float4*)&g_obuf[(size_t)d*CC] + lane) = o;
}

// =================== 128x128x16 double-buffered fp32 GEMM, 8x8 microtile ===================
// MODE 0: C = A@B + bias               (gemm1: obuf[M,K=128] @ W1 -> h1[M,256])
// MODE 1: C += relu(LN(A))@B + bias    (gemm2: LN+relu fused on A=g_h1, residual into xbuf)
template<int MODE>
__device__ __forceinline__ void gemm128(const float* __restrict__ A, const float* __restrict__ B,
                                        const float* __restrict__ bias, float* __restrict__ Cout,
                                        int M, int Nn, int K,
                                        const float* __restrict__ lnw, const float* __restrict__ lnb){
    __shared__ float As[2][16][132];
    __shared__ float Bs[2][16][132];
    int tid = threadIdx.x;                    // 256
    int bm = blockIdx.y*128, bn = blockIdx.x*128;
    int ty = tid >> 4, tx = tid & 15;

    float mean = 0.f, inv = 0.f;
    if (MODE == 1){
        double cnt = (double)M * (double)K;   // total elements of h1
        double mu  = g_lnstat[0]/cnt;
        double var = g_lnstat[1]/cnt - mu*mu;
        mean = (float)mu;
        inv  = 1.f/((float)sqrt(fmax(var, 0.0)) + 1e-5f);
    }

    // loader indices
    int a_r  = tid >> 2;          // 0..63 (+64)
    int a_k  = (tid & 3)*4;
    int b_k  = tid >> 5;          // 0..7 (+8)
    int b_c  = (tid & 31)*4;

    float4 ra[2], rb[2];
    auto ldA = [&](int k0){
        #pragma unroll
        for (int i = 0; i < 2; i++){
            int row = bm + a_r + i*64;
            float4 av = make_float4(0.f,0.f,0.f,0.f);
            if (row < M){
                av = *(const float4*)&A[(size_t)row*K + k0 + a_k];
                if (MODE == 1){
                    int c = k0 + a_k;
                    av.x = fmaxf(fmaf((av.x-mean)*inv, __ldg(&lnw[c+0]), __ldg(&lnb[c+0])), 0.f);
                    av.y = fmaxf(fmaf((av.y-mean)*inv, __ldg(&lnw[c+1]), __ldg(&lnb[c+1])), 0.f);
                    av.z = fmaxf(fmaf((av.z-mean)*inv, __ldg(&lnw[c+2]), __ldg(&lnb[c+2])), 0.f);
                    av.w = fmaxf(fmaf((av.w-mean)*inv, __ldg(&lnw[c+3]), __ldg(&lnb[c+3])), 0.f);
                }
            }
            ra[i] = av;
        }
    };
    auto ldB = [&](int k0){
        #pragma unroll
        for (int i = 0; i < 2; i++)
            rb[i] = *(const float4*)&B[(size_t)(k0 + b_k + i*8)*Nn + bn + b_c];
    };
    auto stAB = [&](int buf){
        #pragma unroll
        for (int i = 0; i < 2; i++){
            As[buf][a_k+0][a_r + i*64] = ra[i].x;
            As[buf][a_k+1][a_r + i*64] = ra[i].y;
            As[buf][a_k+2][a_r + i*64] = ra[i].z;
            As[buf][a_k+3][a_r + i*64] = ra[i].w;
            *(float4*)&Bs[buf][b_k + i*8][b_c] = rb[i];
        }
    };

    float acc[8][8];
    #pragma unroll
    for (int i = 0; i < 8; i++)
        #pragma unroll
        for (int j = 0; j < 8; j++) acc[i][j] = 0.f;

    ldA(0); ldB(0); stAB(0);
    __syncthreads();

    int KT = K >> 4;
    for (int kt = 0; kt < KT; kt++){
        int cbuf = kt & 1;
        if (kt + 1 < KT){ ldA((kt+1)<<4); ldB((kt+1)<<4); }
        #pragma unroll
        for (int k = 0; k < 16; k++){
            float4 a0 = *(const float4*)&As[cbuf][k][ty*8];
            float4 a1 = *(const float4*)&As[cbuf][k][ty*8+4];
            float4 b0 = *(const float4*)&Bs[cbuf][k][tx*8];
            float4 b1 = *(const float4*)&Bs[cbuf][k][tx*8+4];
            float a[8] = {a0.x,a0.y,a0.z,a0.w,a1.x,a1.y,a1.z,a1.w};
            float b[8] = {b0.x,b0.y,b0.z,b0.w,b1.x,b1.y,b1.z,b1.w};
            #pragma unroll
            for (int i = 0; i < 8; i++)
                #pragma unroll
                for (int j = 0; j < 8; j++) acc[i][j] = fmaf(a[i], b[j], acc[i][j]);
        }
        if (kt + 1 < KT){ stAB((kt+1) & 1); }
        __syncthreads();
    }

    float bv[8];
    #pragma unroll
    for (int j = 0; j < 8; j++) bv[j] = bias[bn + tx*8 + j];
    #pragma unroll
    for (int i = 0; i < 8; i++){
        int row = bm + ty*8 + i;
        if (row >= M) continue;
        size_t base = (size_t)row*Nn + bn + tx*8;
        #pragma unroll
        for (int h = 0; h < 2; h++){
            float4 r;
            r.x = acc[i][h*4+0] + bv[h*4+0];
            r.y = acc[i][h*4+1] + bv[h*4+1];
            r.z = acc[i][h*4+2] + bv[h*4+2];
            r.w = acc[i][h*4+3] + bv[h*4+3];
            if (MODE == 1){
                float4 old = *(float4*)&Cout[base + h*4];
                r.x += old.x; r.y += old.y; r.z += old.z; r.w += old.w;
            }
            *(float4*)&Cout[base + h*4] = r;
        }
    }
}

__global__ void __launch_bounds__(256) k_gemm1(const float* __restrict__ B, const float* __restrict__ bias, int M){
    gemm128<0>(g_obuf, B, bias, g_h1, M, HH, CC, nullptr, nullptr);
}
__global__ void __launch_bounds__(256) k_gemm2(const float* __restrict__ B, const float* __restrict__ bias,
                                               const float* __restrict__ lnw, const float* __restrict__ lnb, int M){
    gemm128<1>(g_h1, B, bias, g_xbuf, M, CC, HH, lnw, lnb);
}

__global__ void k_ln_stats(int total){
    double s1 = 0.0, s2 = 0.0;
    for (int i = blockIdx.x*blockDim.x + threadIdx.x; i < total; i += gridDim.x*blockDim.x){
        float v = g_h1[i];
        s1 += (double)v; s2 += (double)v*(double)v;
    }
    __shared__ double sh1[256], sh2[256];
    int t = threadIdx.x;
    sh1[t] = s1; sh2[t] = s2; __syncthreads();
    for (int o = 128; o > 0; o >>= 1){
        if (t < o){ sh1[t] += sh1[t+o]; sh2[t] += sh2[t+o]; }
        __syncthreads();
    }
    if (t == 0){ atomicAdd(&g_lnstat[0], sh1[0]); atomicAdd(&g_lnstat[1], sh2[0]); }
}

// out[n] = x[n,:] . lin_w + lin_b  (warp per node)
__global__ void k_final(const float* __restrict__ lw, const float* __restrict__ lb,
                        float* __restrict__ out, int N){
    int r = blockIdx.x*8 + (threadIdx.x >> 5);
    if (r >= N) return;
    int lane = threadIdx.x & 31;
    float4 v = ((const float4*)&g_xbuf[(size_t)r*CC])[lane];
    float4 w = ((const float4*)lw)[lane];
    float s = v.x*w.x + v.y*w.y + v.z*w.z + v.w*w.w;
    #pragma unroll
    for (int o = 16; o > 0; o >>= 1) s += __shfl_xor_sync(0xFFFFFFFFu, s, o);
    if (lane == 0) out[r] = s + lb[0];
}

extern "C" void kernel_launch(void* const* d_in, const int* in_sizes, int n_in,
                              void* d_out, int out_size){
    const float* x    = (const float*)d_in[0];
    const int*   src  = (const int*)  d_in[1];
    const int*   dst  = (const int*)  d_in[2];
    const float* W1   = (const float*)d_in[3];
    const float* b1   = (const float*)d_in[4];
    const float* lnw  = (const float*)d_in[5];
    const float* lnb  = (const float*)d_in[6];
    const float* W2   = (const float*)d_in[7];
    const float* b2   = (const float*)d_in[8];
    const float* t    = (const float*)d_in[9];
    const float* gnw  = (const float*)d_in[10];
    const float* gnb  = (const float*)d_in[11];
    const float* gna  = (const float*)d_in[12];
    const float* linw = (const float*)d_in[13];
    const float* linb = (const float*)d_in[14];
    float* out = (float*)d_out;

    int N = in_sizes[0]/CC;
    int E = in_sizes[1];
    int totalNC = N*CC;
    int totalNH = N*HH;
    int nc_blocks = (totalNC + 255)/256;
    int e_blocks  = (E + 255)/256;

    // CSR build (per launch; dst fixed across layers)
    k_zero_deg<<<(N+255)/256, 256>>>(N);
    k_hist<<<e_blocks, 256>>>(dst, E);
    k_scan<<<1, 1024>>>(N);
    k_zero_deg<<<(N+255)/256, 256>>>(N);
    k_scatter<<<e_blocks, 256>>>(src, dst, E);

    k_copy<<<nc_blocks, 256>>>(x, totalNC);

    for (int l = 0; l < 4; l++){
        k_zero_stats<<<1, 256>>>();
        k_gn_stats<<<512, CC>>>(N);
        k_gn_apply<<<nc_blocks, 256>>>(gnw, gnb, gna, l, N);
        k_agg<<<(N+7)/8, 256>>>(t, l, N);
        k_gemm1<<<dim3(HH/128, (N+127)/128), 256>>>(W1 + (size_t)l*CC*HH, b1 + (size_t)l*HH, N);
        k_ln_stats<<<1024, 256>>>(totalNH);
        k_gemm2<<<dim3(CC/128, (N+127)/128), 256>>>(W2 + (size_t)l*HH*CC, b2 + (size_t)l*CC,
                                                    lnw + (size_t)l*HH, lnb + (size_t)l*HH, N);
    }
    k_final<<<(N+7)/8, 256>>>(linw, linb, out, N);
}

// round 5
// speedup vs baseline: 1.2106x; 1.2106x over previous
#include <cuda_runtime.h>
#include <math.h>
#include <stdint.h>

#define NN 50000
#define CC 128
#define HH 256
#define EE 600000

// ---- persistent scratch ----
__device__ float  g_xbuf[NN*CC];   // running residual x
__device__ float  g_hbuf[NN*CC];   // after graphnorm+relu (gen_conv input)
__device__ float  g_obuf[NN*CC];   // agg + root (MLP input)
__device__ float  g_h1  [NN*HH];   // hidden after W1 (raw; LN fused into gemm2 loader)
__device__ float  g_gnstat[2*CC];
__device__ double g_lnstat[2];
__device__ int    g_deg [NN];
__device__ int    g_off [NN+1];
__device__ int    g_esrc[EE];

// ---- packed f32x2 helpers (Blackwell family PTX; NOT an 'a'-feature) ----
__device__ __forceinline__ unsigned long long pack2(float x, float y){
    unsigned long long r;
    asm("mov.b64 %0, {%1, %2};" : "=l"(r) : "f"(x), "f"(y));
    return r;
}
__device__ __forceinline__ void unpack2(unsigned long long v, float& x, float& y){
    asm("mov.b64 {%0, %1}, %2;" : "=f"(x), "=f"(y) : "l"(v));
}
__device__ __forceinline__ unsigned long long pfma(unsigned long long a, unsigned long long b,
                                                   unsigned long long c){
    unsigned long long r;
    asm("fma.rn.f32x2 %0, %1, %2, %3;" : "=l"(r) : "l"(a), "l"(b), "l"(c));
    return r;
}

// =================== CSR build (dst-grouped), once per launch ===================
__global__ void k_zero_deg(int N){
    for (int i = blockIdx.x*blockDim.x + threadIdx.x; i < N; i += gridDim.x*blockDim.x)
        g_deg[i] = 0;
}
__global__ void k_hist(const int* __restrict__ dst, int E){
    for (int e = blockIdx.x*blockDim.x + threadIdx.x; e < E; e += gridDim.x*blockDim.x)
        atomicAdd(&g_deg[dst[e]], 1);
}
__global__ void k_scan(int N){
    __shared__ int part[1024];
    int t = threadIdx.x;
    int chunk = (N + 1023)/1024;
    int beg = t*chunk, end = min(beg + chunk, N);
    int s = 0;
    for (int i = beg; i < end; i++) s += g_deg[i];
    part[t] = s; __syncthreads();
    for (int o = 1; o < 1024; o <<= 1){
        int v = (t >= o) ? part[t-o] : 0;
        __syncthreads();
        part[t] += v;
        __syncthreads();
    }
    int base = (t == 0) ? 0 : part[t-1];
    for (int i = beg; i < end; i++){ g_off[i] = base; base += g_deg[i]; }
    if (t == 1023) g_off[N] = part[1023];
}
__global__ void k_scatter(const int* __restrict__ src, const int* __restrict__ dst, int E){
    for (int e = blockIdx.x*blockDim.x + threadIdx.x; e < E; e += gridDim.x*blockDim.x){
        int d = dst[e];
        int pos = atomicAdd(&g_deg[d], 1);
        g_esrc[g_off[d] + pos] = src[e];
    }
}

// =================== elementwise / norm kernels ===================
__global__ void k_copy(const float* __restrict__ x, int n){
    for (int i = blockIdx.x*blockDim.x + threadIdx.x; i < n; i += gridDim.x*blockDim.x)
        g_xbuf[i] = x[i];
}
__global__ void k_zero_stats(){
    int t = threadIdx.x;
    if (t < 2*CC) g_gnstat[t] = 0.f;
    if (t == 0){ g_lnstat[0] = 0.0; g_lnstat[1] = 0.0; }
}
__global__ void k_gn_stats(int N){
    int c = threadIdx.x;          // 128 threads = channels
    float s1 = 0.f, s2 = 0.f;
    for (int r = blockIdx.x; r < N; r += gridDim.x){
        float v = g_xbuf[(size_t)r*CC + c];
        s1 += v; s2 += v*v;
    }
    atomicAdd(&g_gnstat[c],    s1);
    atomicAdd(&g_gnstat[CC+c], s2);
}
__global__ void k_gn_apply(const float* __restrict__ gw, const float* __restrict__ gb,
                           const float* __restrict__ ga, int l, int N){
    int total = N*CC;
    float invN = 1.f/(float)N;
    for (int i = blockIdx.x*blockDim.x + threadIdx.x; i < total; i += gridDim.x*blockDim.x){
        int c = i & (CC-1);
        float mean = g_gnstat[c]*invN;
        float a = ga[l*CC+c];
        // var = E[(x - a*mean)^2] = E[x^2] - 2a*mean^2 + a^2*mean^2
        float var = g_gnstat[CC+c]*invN - 2.f*a*mean*mean + a*a*mean*mean;
        float o = g_xbuf[i] - a*mean;
        float y = gw[l*CC+c]*o*rsqrtf(var + 1e-5f) + gb[l*CC+c];
        g_hbuf[i] = fmaxf(y, 0.f);
    }
}

// =================== fused softmax-aggregate (CSR gather, no atomics) ===================
__global__ void k_agg(const float* __restrict__ t, int l, int N){
    int d = blockIdx.x*8 + (threadIdx.x >> 5);
    if (d >= N) return;
    int lane = threadIdx.x & 31;
    int beg = g_off[d], end = g_off[d+1];
    float tv = t[l];
    float4 num = make_float4(0.f,0.f,0.f,0.f);
    float4 den = make_float4(0.f,0.f,0.f,0.f);
    int j = beg;
    for (; j + 1 < end; j += 2){
        int s0 = g_esrc[j], s1 = g_esrc[j+1];
        float4 v0 = *((const float4*)&g_hbuf[(size_t)s0*CC] + lane);
        float4 v1 = *((const float4*)&g_hbuf[(size_t)s1*CC] + lane);
        float m0x=v0.x+1e-7f, m0y=v0.y+1e-7f, m0z=v0.z+1e-7f, m0w=v0.w+1e-7f;
        float m1x=v1.x+1e-7f, m1y=v1.y+1e-7f, m1z=v1.z+1e-7f, m1w=v1.w+1e-7f;
        float e0x=__expf(tv*m0x), e0y=__expf(tv*m0y), e0z=__expf(tv*m0z), e0w=__expf(tv*m0w);
        float e1x=__expf(tv*m1x), e1y=__expf(tv*m1y), e1z=__expf(tv*m1z), e1w=__expf(tv*m1w);
        num.x = fmaf(m0x,e0x,fmaf(m1x,e1x,num.x)); den.x += e0x+e1x;
        num.y = fmaf(m0y,e0y,fmaf(m1y,e1y,num.y)); den.y += e0y+e1y;
        num.z = fmaf(m0z,e0z,fmaf(m1z,e1z,num.z)); den.z += e0z+e1z;
        num.w = fmaf(m0w,e0w,fmaf(m1w,e1w,num.w)); den.w += e0w+e1w;
    }
    if (j < end){
        int s0 = g_esrc[j];
        float4 v0 = *((const float4*)&g_hbuf[(size_t)s0*CC] + lane);
        float mx=v0.x+1e-7f, my=v0.y+1e-7f, mz=v0.z+1e-7f, mw=v0.w+1e-7f;
        float ex=__expf(tv*mx), ey=__expf(tv*my), ez=__expf(tv*mz), ew=__expf(tv*mw);
        num.x = fmaf(mx,ex,num.x); den.x += ex;
        num.y = fmaf(my,ey,num.y); den.y += ey;
        num.z = fmaf(mz,ez,num.z); den.z += ez;
        num.w = fmaf(mw,ew,num.w); den.w += ew;
    }
    float4 h = *((const float4*)&g_hbuf[(size_t)d*CC] + lane);
    float4 o;
    o.x = num.x/(den.x+1e-16f) + h.x;
    o.y = num.y/(den.y+1e-16f) + h.y;
    o.z = num.z/(den.z+1e-16f) + h.z;
    o.w = num.w/(den.w+1e-16f) + h.w;
    *((float4*)&g_obuf[(size_t)d*CC] + lane) = o;
}

// =================== 128x128x16 double-buffered GEMM, 8x8 microtile, f32x2 FMA ===================
// MODE 0: g_h1 = obuf@W1 + b1, fused global-LN statistics
// MODE 1: g_xbuf += relu(LN(g_h1))@W2 + b2 (LN+relu fused into A loader)
template<int MODE>
__device__ __forceinline__ void gemm128(const float* __restrict__ A, const float* __restrict__ B,
                                        const float* __restrict__ bias, float* __restrict__ Cout,
                                        int M, int Nn, int K,
                                        const float* __restrict__ lnw, const float* __restrict__ lnb){
    __shared__ float As[2][16][132];
    __shared__ float Bs[2][16][132];
    int tid = threadIdx.x;                    // 256
    int bm = blockIdx.y*128, bn = blockIdx.x*128;
    int ty = tid >> 4, tx = tid & 15;

    float mean = 0.f, inv = 0.f;
    if (MODE == 1){
        double cnt = (double)M * (double)K;
        double mu  = g_lnstat[0]/cnt;
        double var = g_lnstat[1]/cnt - mu*mu;
        mean = (float)mu;
        inv  = 1.f/((float)sqrt(fmax(var, 0.0)) + 1e-5f);
    }

    int a_r  = tid >> 2;          // 0..63 (+64)
    int a_k  = (tid & 3)*4;
    int b_k  = tid >> 5;          // 0..7 (+8)
    int b_c  = (tid & 31)*4;

    float4 ra[2], rb[2];
    auto ldA = [&](int k0){
        #pragma unroll
        for (int i = 0; i < 2; i++){
            int row = bm + a_r + i*64;
            float4 av = make_float4(0.f,0.f,0.f,0.f);
            if (row < M){
                av = *(const float4*)&A[(size_t)row*K + k0 + a_k];
                if (MODE == 1){
                    int c = k0 + a_k;
                    av.x = fmaxf(fmaf((av.x-mean)*inv, __ldg(&lnw[c+0]), __ldg(&lnb[c+0])), 0.f);
                    av.y = fmaxf(fmaf((av.y-mean)*inv, __ldg(&lnw[c+1]), __ldg(&lnb[c+1])), 0.f);
                    av.z = fmaxf(fmaf((av.z-mean)*inv, __ldg(&lnw[c+2]), __ldg(&lnb[c+2])), 0.f);
                    av.w = fmaxf(fmaf((av.w-mean)*inv, __ldg(&lnw[c+3]), __ldg(&lnb[c+3])), 0.f);
                }
            }
            ra[i] = av;
        }
    };
    auto ldB = [&](int k0){
        #pragma unroll
        for (int i = 0; i < 2; i++)
            rb[i] = *(const float4*)&B[(size_t)(k0 + b_k + i*8)*Nn + bn + b_c];
    };
    auto stAB = [&](int buf){
        #pragma unroll
        for (int i = 0; i < 2; i++){
            As[buf][a_k+0][a_r + i*64] = ra[i].x;
            As[buf][a_k+1][a_r + i*64] = ra[i].y;
            As[buf][a_k+2][a_r + i*64] = ra[i].z;
            As[buf][a_k+3][a_r + i*64] = ra[i].w;
            *(float4*)&Bs[buf][b_k + i*8][b_c] = rb[i];
        }
    };

    unsigned long long acc[8][4];
    #pragma unroll
    for (int i = 0; i < 8; i++)
        #pragma unroll
        for (int j = 0; j < 4; j++) acc[i][j] = 0ull;

    ldA(0); ldB(0); stAB(0);
    __syncthreads();

    int KT = K >> 4;
    for (int kt = 0; kt < KT; kt++){
        int cbuf = kt & 1;
        if (kt + 1 < KT){ ldA((kt+1)<<4); ldB((kt+1)<<4); }
        #pragma unroll
        for (int k = 0; k < 16; k++){
            float4 a0 = *(const float4*)&As[cbuf][k][ty*8];
            float4 a1 = *(const float4*)&As[cbuf][k][ty*8+4];
            float4 b0 = *(const float4*)&Bs[cbuf][k][tx*8];
            float4 b1 = *(const float4*)&Bs[cbuf][k][tx*8+4];
            unsigned long long bp[4] = { pack2(b0.x,b0.y), pack2(b0.z,b0.w),
                                         pack2(b1.x,b1.y), pack2(b1.z,b1.w) };
            float a[8] = {a0.x,a0.y,a0.z,a0.w,a1.x,a1.y,a1.z,a1.w};
            #pragma unroll
            for (int i = 0; i < 8; i++){
                unsigned long long ad = pack2(a[i], a[i]);
                #pragma unroll
                for (int j = 0; j < 4; j++) acc[i][j] = pfma(ad, bp[j], acc[i][j]);
            }
        }
        if (kt + 1 < KT){ stAB((kt+1) & 1); }
        __syncthreads();
    }

    float bv[8];
    #pragma unroll
    for (int j = 0; j < 8; j++) bv[j] = bias[bn + tx*8 + j];

    float s1 = 0.f, s2 = 0.f;   // LN stats (MODE 0)
    #pragma unroll
    for (int i = 0; i < 8; i++){
        int row = bm + ty*8 + i;
        if (row >= M) continue;
        size_t base = (size_t)row*Nn + bn + tx*8;
        #pragma unroll
        for (int h = 0; h < 2; h++){
            float4 r;
            unpack2(acc[i][h*2+0], r.x, r.y);
            unpack2(acc[i][h*2+1], r.z, r.w);
            r.x += bv[h*4+0]; r.y += bv[h*4+1];
            r.z += bv[h*4+2]; r.w += bv[h*4+3];
            if (MODE == 0){
                s1 += r.x + r.y + r.z + r.w;
                s2 += r.x*r.x + r.y*r.y + r.z*r.z + r.w*r.w;
            } else {
                float4 old = *(float4*)&Cout[base + h*4];
                r.x += old.x; r.y += old.y; r.z += old.z; r.w += old.w;
            }
            *(float4*)&Cout[base + h*4] = r;
        }
    }
    if (MODE == 0){
        #pragma unroll
        for (int o = 16; o > 0; o >>= 1){
            s1 += __shfl_xor_sync(0xFFFFFFFFu, s1, o);
            s2 += __shfl_xor_sync(0xFFFFFFFFu, s2, o);
        }
        if ((tid & 31) == 0){
            atomicAdd(&g_lnstat[0], (double)s1);
            atomicAdd(&g_lnstat[1], (double)s2);
        }
    }
}

__global__ void __launch_bounds__(256) k_gemm1(const float* __restrict__ B, const float* __restrict__ bias, int M){
    gemm128<0>(g_obuf, B, bias, g_h1, M, HH, CC, nullptr, nullptr);
}
__global__ void __launch_bounds__(256) k_gemm2(const float* __restrict__ B, const float* __restrict__ bias,
                                               const float* __restrict__ lnw, const float* __restrict__ lnb, int M){
    gemm128<1>(g_h1, B, bias, g_xbuf, M, CC, HH, lnw, lnb);
}

// out[n] = x[n,:] . lin_w + lin_b  (warp per node)
__global__ void k_final(const float* __restrict__ lw, const float* __restrict__ lb,
                        float* __restrict__ out, int N){
    int r = blockIdx.x*8 + (threadIdx.x >> 5);
    if (r >= N) return;
    int lane = threadIdx.x & 31;
    float4 v = ((const float4*)&g_xbuf[(size_t)r*CC])[lane];
    float4 w = ((const float4*)lw)[lane];
    float s = v.x*w.x + v.y*w.y + v.z*w.z + v.w*w.w;
    #pragma unroll
    for (int o = 16; o > 0; o >>= 1) s += __shfl_xor_sync(0xFFFFFFFFu, s, o);
    if (lane == 0) out[r] = s + lb[0];
}

extern "C" void kernel_launch(void* const* d_in, const int* in_sizes, int n_in,
                              void* d_out, int out_size){
    const float* x    = (const float*)d_in[0];
    const int*   src  = (const int*)  d_in[1];
    const int*   dst  = (const int*)  d_in[2];
    const float* W1   = (const float*)d_in[3];
    const float* b1   = (const float*)d_in[4];
    const float* lnw  = (const float*)d_in[5];
    const float* lnb  = (const float*)d_in[6];
    const float* W2   = (const float*)d_in[7];
    const float* b2   = (const float*)d_in[8];
    const float* t    = (const float*)d_in[9];
    const float* gnw  = (const float*)d_in[10];
    const float* gnb  = (const float*)d_in[11];
    const float* gna  = (const float*)d_in[12];
    const float* linw = (const float*)d_in[13];
    const float* linb = (const float*)d_in[14];
    float* out = (float*)d_out;

    int N = in_sizes[0]/CC;
    int E = in_sizes[1];
    int totalNC = N*CC;
    int nc_blocks = (totalNC + 255)/256;
    int e_blocks  = (E + 255)/256;

    // CSR build (per launch; deterministic)
    k_zero_deg<<<(N+255)/256, 256>>>(N);
    k_hist<<<e_blocks, 256>>>(dst, E);
    k_scan<<<1, 1024>>>(N);
    k_zero_deg<<<(N+255)/256, 256>>>(N);
    k_scatter<<<e_blocks, 256>>>(src, dst, E);

    k_copy<<<nc_blocks, 256>>>(x, totalNC);

    for (int l = 0; l < 4; l++){
        k_zero_stats<<<1, 256>>>();
        k_gn_stats<<<512, CC>>>(N);
        k_gn_apply<<<nc_blocks, 256>>>(gnw, gnb, gna, l, N);
        k_agg<<<(N+7)/8, 256>>>(t, l, N);
        k_gemm1<<<dim3(HH/128, (N+127)/128), 256>>>(W1 + (size_t)l*CC*HH, b1 + (size_t)l*HH, N);
        k_gemm2<<<dim3(CC/128, (N+127)/128), 256>>>(W2 + (size_t)l*HH*CC, b2 + (size_t)l*CC,
                                                    lnw + (size_t)l*HH, lnb + (size_t)l*HH, N);
    }
    k_final<<<(N+7)/8, 256>>>(linw, linb, out, N);
}